// round 3
// baseline (speedup 1.0000x reference)
#include <cuda_runtime.h>
#include <math.h>

// Problem dims
#define Bdim   4
#define Sdim   2048
#define DINdim 1024
#define DMdim  1024
#define Hdim   16
#define DPT    64
#define BHdim  (Bdim*Hdim)

#define OUT_ELEMS  (Bdim*Sdim*DMdim)                 // 8388608
#define ATTN_ELEMS ((long long)BHdim*Sdim*Sdim)      // 268435456

#define CHUNK_BH   4                                  // fallback chunk size

// Scratch (allocation-free: __device__ globals). Total ~198 MB.
__device__ float g_qh[(size_t)BHdim*Sdim*DPT];       // (B,H,S,D)  33.5 MB
__device__ float g_kh[(size_t)BHdim*Sdim*DPT];
__device__ float g_vh[(size_t)BHdim*Sdim*DPT];
__device__ float g_concat[(size_t)Bdim*Sdim*DMdim];  // (B,S,DM)   33.5 MB
__device__ float g_attn_chunk[(size_t)CHUNK_BH*Sdim*Sdim]; // 64 MB fallback scratch

// ---------------------------------------------------------------------------
// Generic C = A(MxK) @ W(NxK)^T + bias, K=1024, 128x128 tile, 8x8 per thread
// head_layout: scatter into (B,H,S,DPT); else plain row-major (M x N)
// ---------------------------------------------------------------------------
__global__ void __launch_bounds__(256)
sgemm128(const float* __restrict__ A, const float* __restrict__ W,
         const float* __restrict__ bias, float* __restrict__ out,
         int head_layout)
{
    const int K = 1024;
    __shared__ float As[16][132];
    __shared__ float Bs[16][132];
    int t  = threadIdx.x;
    int m0 = blockIdx.y * 128;
    int n0 = blockIdx.x * 128;
    int lr = t >> 1;
    int lc = (t & 1) * 4;
    const float* Ap = A + (size_t)(m0 + lr) * K + lc;
    const float* Wp = W + (size_t)(n0 + lr) * K + lc;
    int ty = t >> 4, tx = t & 15;

    float acc[8][8];
    #pragma unroll
    for (int i = 0; i < 8; i++)
        #pragma unroll
        for (int j = 0; j < 8; j++) acc[i][j] = 0.f;

    // prologue loads for kt = 0
    float4 a0 = *(const float4*)(Ap);
    float4 a1 = *(const float4*)(Ap + 8);
    float4 b0 = *(const float4*)(Wp);
    float4 b1 = *(const float4*)(Wp + 8);

    for (int kt = 0; kt < K; kt += 16) {
        __syncthreads();
        As[lc+0][lr]=a0.x; As[lc+1][lr]=a0.y; As[lc+2][lr]=a0.z; As[lc+3][lr]=a0.w;
        As[lc+8][lr]=a1.x; As[lc+9][lr]=a1.y; As[lc+10][lr]=a1.z; As[lc+11][lr]=a1.w;
        Bs[lc+0][lr]=b0.x; Bs[lc+1][lr]=b0.y; Bs[lc+2][lr]=b0.z; Bs[lc+3][lr]=b0.w;
        Bs[lc+8][lr]=b1.x; Bs[lc+9][lr]=b1.y; Bs[lc+10][lr]=b1.z; Bs[lc+11][lr]=b1.w;
        __syncthreads();
        // issue next tile's loads early so they overlap the FMA loop
        if (kt + 16 < K) {
            a0 = *(const float4*)(Ap + kt + 16);
            a1 = *(const float4*)(Ap + kt + 24);
            b0 = *(const float4*)(Wp + kt + 16);
            b1 = *(const float4*)(Wp + kt + 24);
        }
        #pragma unroll
        for (int k = 0; k < 16; k++) {
            float a[8], b[8];
            *(float4*)(a)   = *(const float4*)&As[k][ty*8];
            *(float4*)(a+4) = *(const float4*)&As[k][ty*8+4];
            *(float4*)(b)   = *(const float4*)&Bs[k][tx*8];
            *(float4*)(b+4) = *(const float4*)&Bs[k][tx*8+4];
            #pragma unroll
            for (int i = 0; i < 8; i++)
                #pragma unroll
                for (int j = 0; j < 8; j++)
                    acc[i][j] = fmaf(a[i], b[j], acc[i][j]);
        }
    }

    #pragma unroll
    for (int i = 0; i < 8; i++) {
        int m = m0 + ty*8 + i;
        #pragma unroll
        for (int j = 0; j < 8; j++) {
            int n = n0 + tx*8 + j;
            float v = acc[i][j] + bias[n];
            if (head_layout) {
                int bb = m >> 11, s = m & 2047;
                int h  = n >> 6,  d = n & 63;
                out[(((size_t)(bb*Hdim + h))*Sdim + s)*DPT + d] = v;
            } else {
                out[(size_t)m * DMdim + n] = v;
            }
        }
    }
}

// ---------------------------------------------------------------------------
// QK^T: per (b,h): logits(2048x2048) = Q(2048x64) @ K(2048x64)^T * 0.125
//       + mask[b][k]*(-1e9). bh = bh_base + blockIdx.z; attn indexed by
//       blockIdx.z (local slice index in the provided buffer).
// ---------------------------------------------------------------------------
__global__ void __launch_bounds__(256)
qk_kernel(const float* __restrict__ mask, float* __restrict__ attn, int bh_base)
{
    __shared__ float As[16][132];
    __shared__ float Bs[16][132];
    int t  = threadIdx.x;
    int zl = blockIdx.z;
    int bh = bh_base + zl;
    int m0 = blockIdx.y * 128;
    int n0 = blockIdx.x * 128;
    const float* Q  = g_qh + (size_t)bh * Sdim * DPT;
    const float* Kh = g_kh + (size_t)bh * Sdim * DPT;
    int lr = t >> 1;
    int lc = (t & 1) * 4;
    const float* Ap = Q  + (size_t)(m0 + lr) * DPT + lc;
    const float* Wp = Kh + (size_t)(n0 + lr) * DPT + lc;
    int ty = t >> 4, tx = t & 15;

    float acc[8][8];
    #pragma unroll
    for (int i = 0; i < 8; i++)
        #pragma unroll
        for (int j = 0; j < 8; j++) acc[i][j] = 0.f;

    #pragma unroll
    for (int kt = 0; kt < DPT; kt += 16) {
        float4 a0 = *(const float4*)(Ap + kt);
        float4 a1 = *(const float4*)(Ap + kt + 8);
        float4 b0 = *(const float4*)(Wp + kt);
        float4 b1 = *(const float4*)(Wp + kt + 8);
        __syncthreads();
        As[lc+0][lr]=a0.x; As[lc+1][lr]=a0.y; As[lc+2][lr]=a0.z; As[lc+3][lr]=a0.w;
        As[lc+8][lr]=a1.x; As[lc+9][lr]=a1.y; As[lc+10][lr]=a1.z; As[lc+11][lr]=a1.w;
        Bs[lc+0][lr]=b0.x; Bs[lc+1][lr]=b0.y; Bs[lc+2][lr]=b0.z; Bs[lc+3][lr]=b0.w;
        Bs[lc+8][lr]=b1.x; Bs[lc+9][lr]=b1.y; Bs[lc+10][lr]=b1.z; Bs[lc+11][lr]=b1.w;
        __syncthreads();
        #pragma unroll
        for (int k = 0; k < 16; k++) {
            float a[8], b[8];
            *(float4*)(a)   = *(const float4*)&As[k][ty*8];
            *(float4*)(a+4) = *(const float4*)&As[k][ty*8+4];
            *(float4*)(b)   = *(const float4*)&Bs[k][tx*8];
            *(float4*)(b+4) = *(const float4*)&Bs[k][tx*8+4];
            #pragma unroll
            for (int i = 0; i < 8; i++)
                #pragma unroll
                for (int j = 0; j < 8; j++)
                    acc[i][j] = fmaf(a[i], b[j], acc[i][j]);
        }
    }

    const float* mrow = mask + (size_t)(bh >> 4) * Sdim;
    float* orow = attn + (size_t)zl * Sdim * Sdim;
    #pragma unroll
    for (int i = 0; i < 8; i++) {
        int m = m0 + ty*8 + i;
        #pragma unroll
        for (int j = 0; j < 8; j++) {
            int n = n0 + tx*8 + j;
            float v = acc[i][j] * 0.125f + mrow[n] * (-1e9f);
            orow[(size_t)m * Sdim + n] = v;
        }
    }
}

// ---------------------------------------------------------------------------
// Row softmax over S=2048, in place. One block (256 thr) per row; values stay
// in registers (8/thread) -> exactly 1 read + 1 write per element.
// ---------------------------------------------------------------------------
__global__ void __launch_bounds__(256)
softmax_kernel(float* __restrict__ attn)
{
    int q  = blockIdx.x;
    int zl = blockIdx.y;
    float* row = attn + ((size_t)zl * Sdim + q) * Sdim;
    int t = threadIdx.x;

    float v[8];
    *(float4*)(v)   = *(const float4*)&row[t*8];
    *(float4*)(v+4) = *(const float4*)&row[t*8+4];

    float m = v[0];
    #pragma unroll
    for (int i = 1; i < 8; i++) m = fmaxf(m, v[i]);
    #pragma unroll
    for (int o = 16; o > 0; o >>= 1) m = fmaxf(m, __shfl_xor_sync(0xffffffffu, m, o));

    __shared__ float red[8];
    if ((t & 31) == 0) red[t >> 5] = m;
    __syncthreads();
    float M = red[0];
    #pragma unroll
    for (int i = 1; i < 8; i++) M = fmaxf(M, red[i]);
    __syncthreads();

    float s = 0.f;
    #pragma unroll
    for (int i = 0; i < 8; i++) { v[i] = expf(v[i] - M); s += v[i]; }
    #pragma unroll
    for (int o = 16; o > 0; o >>= 1) s += __shfl_xor_sync(0xffffffffu, s, o);
    if ((t & 31) == 0) red[t >> 5] = s;
    __syncthreads();
    float S = 0.f;
    #pragma unroll
    for (int i = 0; i < 8; i++) S += red[i];
    float inv = 1.0f / S;

    #pragma unroll
    for (int i = 0; i < 8; i++) v[i] *= inv;
    *(float4*)&row[t*8]   = *(float4*)(v);
    *(float4*)&row[t*8+4] = *(float4*)(v+4);
}

// ---------------------------------------------------------------------------
// ctx = attn(2048x2048) @ V(2048x64) per (b,h); write into concat (B,S,DM)
// tile: 128 rows x 64 cols, BK=32, thread tile 8x4
// bh = bh_base + blockIdx.y; attn indexed by blockIdx.y (local slice).
// ---------------------------------------------------------------------------
__global__ void __launch_bounds__(256)
pv_kernel(const float* __restrict__ attn, int bh_base)
{
    __shared__ float As[32][132];
    __shared__ float Bs[32][68];
    int t  = threadIdx.x;
    int zl = blockIdx.y;
    int bh = bh_base + zl;
    int m0 = blockIdx.x * 128;
    const float* P = attn + (size_t)zl * Sdim * Sdim;
    const float* V = g_vh + (size_t)bh * Sdim * DPT;

    int arow = t >> 1;
    int ac0  = (t & 1) * 4;
    int ty = t >> 4, tx = t & 15;

    float acc[8][4];
    #pragma unroll
    for (int i = 0; i < 8; i++)
        #pragma unroll
        for (int j = 0; j < 4; j++) acc[i][j] = 0.f;

    for (int kt = 0; kt < Sdim; kt += 32) {
        float4 av[4];
        #pragma unroll
        for (int r = 0; r < 4; r++)
            av[r] = *(const float4*)&P[(size_t)(m0 + arow) * Sdim + kt + ac0 + r*8];
        float4 bv[2];
        #pragma unroll
        for (int rb = 0; rb < 2; rb++) {
            int idx = t*2 + rb;
            int kk = idx >> 4, n4 = idx & 15;
            bv[rb] = *(const float4*)&V[(size_t)(kt + kk) * DPT + n4*4];
        }
        __syncthreads();
        #pragma unroll
        for (int r = 0; r < 4; r++) {
            int kk = ac0 + r*8;
            As[kk+0][arow] = av[r].x; As[kk+1][arow] = av[r].y;
            As[kk+2][arow] = av[r].z; As[kk+3][arow] = av[r].w;
        }
        #pragma unroll
        for (int rb = 0; rb < 2; rb++) {
            int idx = t*2 + rb;
            int kk = idx >> 4, n4 = idx & 15;
            *(float4*)&Bs[kk][n4*4] = bv[rb];
        }
        __syncthreads();
        #pragma unroll
        for (int k = 0; k < 32; k++) {
            float a[8], b[4];
            *(float4*)(a)   = *(const float4*)&As[k][ty*8];
            *(float4*)(a+4) = *(const float4*)&As[k][ty*8+4];
            *(float4*)(b)   = *(const float4*)&Bs[k][tx*4];
            #pragma unroll
            for (int i = 0; i < 8; i++)
                #pragma unroll
                for (int j = 0; j < 4; j++)
                    acc[i][j] = fmaf(a[i], b[j], acc[i][j]);
        }
    }

    int bb = bh >> 4, h = bh & 15;
    #pragma unroll
    for (int i = 0; i < 8; i++) {
        int s = m0 + ty*8 + i;
        float4 o = make_float4(acc[i][0], acc[i][1], acc[i][2], acc[i][3]);
        *(float4*)&g_concat[((size_t)bb * Sdim + s) * DMdim + h*DPT + tx*4] = o;
    }
}

// ---------------------------------------------------------------------------
extern "C" void kernel_launch(void* const* d_in, const int* in_sizes, int n_in,
                              void* d_out, int out_size)
{
    const float* v_in    = (const float*)d_in[0];
    const float* k_in    = (const float*)d_in[1];
    const float* q_in    = (const float*)d_in[2];
    const float* mask    = (const float*)d_in[3];
    const float* wq_w    = (const float*)d_in[4];
    const float* wq_b    = (const float*)d_in[5];
    const float* wk_w    = (const float*)d_in[6];
    const float* wk_b    = (const float*)d_in[7];
    const float* wv_w    = (const float*)d_in[8];
    const float* wv_b    = (const float*)d_in[9];
    const float* dense_w = (const float*)d_in[10];
    const float* dense_b = (const float*)d_in[11];

    float *qh, *kh, *vh, *concat, *attn_chunk;
    cudaGetSymbolAddress((void**)&qh, g_qh);
    cudaGetSymbolAddress((void**)&kh, g_kh);
    cudaGetSymbolAddress((void**)&vh, g_vh);
    cudaGetSymbolAddress((void**)&concat, g_concat);
    cudaGetSymbolAddress((void**)&attn_chunk, g_attn_chunk);

    float* out = (float*)d_out;
    int attn_in_out = ((long long)out_size >= (long long)OUT_ELEMS + ATTN_ELEMS);

    dim3 blk(256);
    dim3 g_gemm(DMdim / 128, (Bdim * Sdim) / 128);   // (8, 64)

    sgemm128<<<g_gemm, blk>>>(q_in, wq_w, wq_b, qh, 1);
    sgemm128<<<g_gemm, blk>>>(k_in, wk_w, wk_b, kh, 1);
    sgemm128<<<g_gemm, blk>>>(v_in, wv_w, wv_b, vh, 1);

    if (attn_in_out) {
        // attn lives in d_out right after `out`
        float* attn = out + OUT_ELEMS;
        qk_kernel<<<dim3(Sdim/128, Sdim/128, BHdim), blk>>>(mask, attn, 0);
        softmax_kernel<<<dim3(Sdim, BHdim), blk>>>(attn);
        pv_kernel<<<dim3(Sdim/128, BHdim), blk>>>(attn, 0);
    } else {
        // chunked fallback through 64 MB static scratch
        for (int c = 0; c < BHdim; c += CHUNK_BH) {
            qk_kernel<<<dim3(Sdim/128, Sdim/128, CHUNK_BH), blk>>>(mask, attn_chunk, c);
            softmax_kernel<<<dim3(Sdim, CHUNK_BH), blk>>>(attn_chunk);
            pv_kernel<<<dim3(Sdim/128, CHUNK_BH), blk>>>(attn_chunk, c);
        }
    }

    sgemm128<<<g_gemm, blk>>>(concat, dense_w, dense_b, out, 0);
}

// round 6
// speedup vs baseline: 2.1037x; 2.1037x over previous
#include <cuda_runtime.h>
#include <math.h>
#include <stdint.h>

// Problem dims
#define Bdim   4
#define Sdim   2048
#define DMdim  1024
#define Hdim   16
#define DPT    64
#define BHdim  (Bdim*Hdim)

#define OUT_ELEMS  (Bdim*Sdim*DMdim)                 // 8388608
#define ATTN_ELEMS ((long long)BHdim*Sdim*Sdim)      // 268435456
#define CHUNK_BH   4

// Scratch (allocation-free: __device__ globals). ~198 MB total.
__device__ float g_qh[(size_t)BHdim*Sdim*DPT];
__device__ float g_kh[(size_t)BHdim*Sdim*DPT];
__device__ float g_vh[(size_t)BHdim*Sdim*DPT];
__device__ float g_concat[(size_t)Bdim*Sdim*DMdim];
__device__ float g_attn_chunk[(size_t)CHUNK_BH*Sdim*Sdim];

// ---------------------------------------------------------------------------
__device__ __forceinline__ uint32_t f2tf(float x) {
    uint32_t r;
    asm("cvt.rna.tf32.f32 %0, %1;" : "=r"(r) : "f"(x));
    return r;
}

__device__ __forceinline__ void mma8(float* c, const uint32_t* a, const uint32_t* b) {
    asm volatile(
        "mma.sync.aligned.m16n8k8.row.col.f32.tf32.tf32.f32 "
        "{%0,%1,%2,%3},{%4,%5,%6,%7},{%8,%9},{%0,%1,%2,%3};\n"
        : "+f"(c[0]), "+f"(c[1]), "+f"(c[2]), "+f"(c[3])
        : "r"(a[0]), "r"(a[1]), "r"(a[2]), "r"(a[3]), "r"(b[0]), "r"(b[1]));
}

// ---------------------------------------------------------------------------
// tf32 GEMM: C(128x128/block) = A(MxK) @ W(NxK)^T (+bias), K=1024
// EPI: 0 = dense row-major (M x DMdim), 1 = head-scatter to (B,H,S,DPT)
// ---------------------------------------------------------------------------
template<int EPI>
__global__ void __launch_bounds__(256)
gemm1024_tf32(const float* __restrict__ A, const float* __restrict__ W,
              const float* __restrict__ bias, float* __restrict__ out)
{
    const int K = 1024;
    __shared__ uint32_t As[16][136];   // [k][m]
    __shared__ uint32_t Bs[16][136];   // [k][n]
    int t = threadIdx.x, lane = t & 31, w = t >> 5;
    int q = lane & 3, r = lane >> 2;
    int m0 = blockIdx.y * 128, n0 = blockIdx.x * 128;
    int wm = (w & 1) * 64, wn = (w >> 1) * 32;
    int lr = t >> 1, lc = (t & 1) * 4;
    const float* Ap = A + (size_t)(m0 + lr) * K + lc;
    const float* Wp = W + (size_t)(n0 + lr) * K + lc;

    float acc[4][4][4];
    #pragma unroll
    for (int i = 0; i < 4; i++)
        #pragma unroll
        for (int j = 0; j < 4; j++)
            #pragma unroll
            for (int v = 0; v < 4; v++) acc[i][j][v] = 0.f;

    float4 pa0 = *(const float4*)Ap,      pa1 = *(const float4*)(Ap + 8);
    float4 pb0 = *(const float4*)Wp,      pb1 = *(const float4*)(Wp + 8);

    for (int kt = 0; kt < K; kt += 16) {
        __syncthreads();
        As[lc+0][lr]=f2tf(pa0.x); As[lc+1][lr]=f2tf(pa0.y); As[lc+2][lr]=f2tf(pa0.z); As[lc+3][lr]=f2tf(pa0.w);
        As[lc+8][lr]=f2tf(pa1.x); As[lc+9][lr]=f2tf(pa1.y); As[lc+10][lr]=f2tf(pa1.z); As[lc+11][lr]=f2tf(pa1.w);
        Bs[lc+0][lr]=f2tf(pb0.x); Bs[lc+1][lr]=f2tf(pb0.y); Bs[lc+2][lr]=f2tf(pb0.z); Bs[lc+3][lr]=f2tf(pb0.w);
        Bs[lc+8][lr]=f2tf(pb1.x); Bs[lc+9][lr]=f2tf(pb1.y); Bs[lc+10][lr]=f2tf(pb1.z); Bs[lc+11][lr]=f2tf(pb1.w);
        __syncthreads();
        if (kt + 16 < K) {
            pa0 = *(const float4*)(Ap + kt + 16); pa1 = *(const float4*)(Ap + kt + 24);
            pb0 = *(const float4*)(Wp + kt + 16); pb1 = *(const float4*)(Wp + kt + 24);
        }
        #pragma unroll
        for (int ks = 0; ks < 2; ks++) {
            uint32_t af[4][4], bf[4][2];
            #pragma unroll
            for (int mt = 0; mt < 4; mt++) {
                af[mt][0] = As[ks*8 + q][wm + mt*16 + r];
                af[mt][1] = As[ks*8 + q][wm + mt*16 + 8 + r];
                af[mt][2] = As[ks*8 + 4 + q][wm + mt*16 + r];
                af[mt][3] = As[ks*8 + 4 + q][wm + mt*16 + 8 + r];
            }
            #pragma unroll
            for (int nt = 0; nt < 4; nt++) {
                bf[nt][0] = Bs[ks*8 + q][wn + nt*8 + r];
                bf[nt][1] = Bs[ks*8 + 4 + q][wn + nt*8 + r];
            }
            #pragma unroll
            for (int mt = 0; mt < 4; mt++)
                #pragma unroll
                for (int nt = 0; nt < 4; nt++)
                    mma8(acc[mt][nt], af[mt], bf[nt]);
        }
    }

    #pragma unroll
    for (int mt = 0; mt < 4; mt++) {
        #pragma unroll
        for (int nt = 0; nt < 4; nt++) {
            int m = m0 + wm + mt*16 + r;
            int n = n0 + wn + nt*8 + 2*q;
            float* a4 = acc[mt][nt];
            float bv0 = bias[n], bv1 = bias[n+1];
            if (EPI == 0) {
                *(float2*)&out[(size_t)m*DMdim + n]     = make_float2(a4[0]+bv0, a4[1]+bv1);
                *(float2*)&out[(size_t)(m+8)*DMdim + n] = make_float2(a4[2]+bv0, a4[3]+bv1);
            } else {
                int bb = m >> 11, s = m & 2047, h = n >> 6, d = n & 63;
                size_t base = ((size_t)(bb*Hdim + h)) * Sdim;
                *(float2*)&out[(base + s)*DPT + d]     = make_float2(a4[0]+bv0, a4[1]+bv1);
                *(float2*)&out[(base + s + 8)*DPT + d] = make_float2(a4[2]+bv0, a4[3]+bv1);
            }
        }
    }
}

// ---------------------------------------------------------------------------
// QK^T (tf32): logits(2048x2048) = Q @ K^T * 0.125 + mask*(-1e9), K=64
// ---------------------------------------------------------------------------
__global__ void __launch_bounds__(256)
qk_tf32(const float* __restrict__ mask, float* __restrict__ attn, int bh_base)
{
    const int K = DPT;
    __shared__ uint32_t As[16][136];
    __shared__ uint32_t Bs[16][136];
    int t = threadIdx.x, lane = t & 31, w = t >> 5;
    int q = lane & 3, r = lane >> 2;
    int zl = blockIdx.z, bh = bh_base + zl;
    int m0 = blockIdx.y * 128, n0 = blockIdx.x * 128;
    int wm = (w & 1) * 64, wn = (w >> 1) * 32;
    int lr = t >> 1, lc = (t & 1) * 4;
    const float* Q  = g_qh + (size_t)bh * Sdim * DPT;
    const float* Kh = g_kh + (size_t)bh * Sdim * DPT;
    const float* Ap = Q  + (size_t)(m0 + lr) * K + lc;
    const float* Wp = Kh + (size_t)(n0 + lr) * K + lc;

    float acc[4][4][4];
    #pragma unroll
    for (int i = 0; i < 4; i++)
        #pragma unroll
        for (int j = 0; j < 4; j++)
            #pragma unroll
            for (int v = 0; v < 4; v++) acc[i][j][v] = 0.f;

    float4 pa0 = *(const float4*)Ap, pa1 = *(const float4*)(Ap + 8);
    float4 pb0 = *(const float4*)Wp, pb1 = *(const float4*)(Wp + 8);

    #pragma unroll
    for (int kt = 0; kt < K; kt += 16) {
        __syncthreads();
        As[lc+0][lr]=f2tf(pa0.x); As[lc+1][lr]=f2tf(pa0.y); As[lc+2][lr]=f2tf(pa0.z); As[lc+3][lr]=f2tf(pa0.w);
        As[lc+8][lr]=f2tf(pa1.x); As[lc+9][lr]=f2tf(pa1.y); As[lc+10][lr]=f2tf(pa1.z); As[lc+11][lr]=f2tf(pa1.w);
        Bs[lc+0][lr]=f2tf(pb0.x); Bs[lc+1][lr]=f2tf(pb0.y); Bs[lc+2][lr]=f2tf(pb0.z); Bs[lc+3][lr]=f2tf(pb0.w);
        Bs[lc+8][lr]=f2tf(pb1.x); Bs[lc+9][lr]=f2tf(pb1.y); Bs[lc+10][lr]=f2tf(pb1.z); Bs[lc+11][lr]=f2tf(pb1.w);
        __syncthreads();
        if (kt + 16 < K) {
            pa0 = *(const float4*)(Ap + kt + 16); pa1 = *(const float4*)(Ap + kt + 24);
            pb0 = *(const float4*)(Wp + kt + 16); pb1 = *(const float4*)(Wp + kt + 24);
        }
        #pragma unroll
        for (int ks = 0; ks < 2; ks++) {
            uint32_t af[4][4], bf[4][2];
            #pragma unroll
            for (int mt = 0; mt < 4; mt++) {
                af[mt][0] = As[ks*8 + q][wm + mt*16 + r];
                af[mt][1] = As[ks*8 + q][wm + mt*16 + 8 + r];
                af[mt][2] = As[ks*8 + 4 + q][wm + mt*16 + r];
                af[mt][3] = As[ks*8 + 4 + q][wm + mt*16 + 8 + r];
            }
            #pragma unroll
            for (int nt = 0; nt < 4; nt++) {
                bf[nt][0] = Bs[ks*8 + q][wn + nt*8 + r];
                bf[nt][1] = Bs[ks*8 + 4 + q][wn + nt*8 + r];
            }
            #pragma unroll
            for (int mt = 0; mt < 4; mt++)
                #pragma unroll
                for (int nt = 0; nt < 4; nt++)
                    mma8(acc[mt][nt], af[mt], bf[nt]);
        }
    }

    const float* mrow = mask + (size_t)(bh >> 4) * Sdim;
    float* orow = attn + (size_t)zl * Sdim * Sdim;
    #pragma unroll
    for (int mt = 0; mt < 4; mt++) {
        #pragma unroll
        for (int nt = 0; nt < 4; nt++) {
            int m = m0 + wm + mt*16 + r;
            int n = n0 + wn + nt*8 + 2*q;
            float* a4 = acc[mt][nt];
            float mk0 = mrow[n] * (-1e9f), mk1 = mrow[n+1] * (-1e9f);
            *(float2*)&orow[(size_t)m*Sdim + n]     = make_float2(a4[0]*0.125f + mk0, a4[1]*0.125f + mk1);
            *(float2*)&orow[(size_t)(m+8)*Sdim + n] = make_float2(a4[2]*0.125f + mk0, a4[3]*0.125f + mk1);
        }
    }
}

// ---------------------------------------------------------------------------
// Row softmax over S=2048, in place (register-resident, 1R+1W per element)
// ---------------------------------------------------------------------------
__global__ void __launch_bounds__(256)
softmax_kernel(float* __restrict__ attn)
{
    int qq = blockIdx.x;
    int zl = blockIdx.y;
    float* row = attn + ((size_t)zl * Sdim + qq) * Sdim;
    int t = threadIdx.x;

    float v[8];
    *(float4*)(v)   = *(const float4*)&row[t*8];
    *(float4*)(v+4) = *(const float4*)&row[t*8+4];

    float m = v[0];
    #pragma unroll
    for (int i = 1; i < 8; i++) m = fmaxf(m, v[i]);
    #pragma unroll
    for (int o = 16; o > 0; o >>= 1) m = fmaxf(m, __shfl_xor_sync(0xffffffffu, m, o));

    __shared__ float red[8];
    if ((t & 31) == 0) red[t >> 5] = m;
    __syncthreads();
    float M = red[0];
    #pragma unroll
    for (int i = 1; i < 8; i++) M = fmaxf(M, red[i]);
    __syncthreads();

    float s = 0.f;
    #pragma unroll
    for (int i = 0; i < 8; i++) { v[i] = expf(v[i] - M); s += v[i]; }
    #pragma unroll
    for (int o = 16; o > 0; o >>= 1) s += __shfl_xor_sync(0xffffffffu, s, o);
    if ((t & 31) == 0) red[t >> 5] = s;
    __syncthreads();
    float S = 0.f;
    #pragma unroll
    for (int i = 0; i < 8; i++) S += red[i];
    float inv = 1.0f / S;

    #pragma unroll
    for (int i = 0; i < 8; i++) v[i] *= inv;
    *(float4*)&row[t*8]   = *(float4*)(v);
    *(float4*)&row[t*8+4] = *(float4*)(v+4);
}

// ---------------------------------------------------------------------------
// PV (tf32): ctx(128x64/block) = attn(2048x2048) @ V(2048x64); BK=32
// Writes into g_concat (B,S,DM) head-interleaved.
// ---------------------------------------------------------------------------
__global__ void __launch_bounds__(256)
pv_tf32(const float* __restrict__ attn, int bh_base)
{
    __shared__ uint32_t Ps[32][136];   // [k][m]
    __shared__ uint32_t Vs[32][72];    // [k][n]
    int t = threadIdx.x, lane = t & 31, w = t >> 5;
    int q = lane & 3, r = lane >> 2;
    int zl = blockIdx.y, bh = bh_base + zl;
    int m0 = blockIdx.x * 128;
    int wm = (w & 3) * 32, wn = (w >> 2) * 32;
    const float* P = attn + (size_t)zl * Sdim * Sdim;
    const float* V = g_vh + (size_t)bh * Sdim * DPT;

    int lr = t >> 1, lc = (t & 1) * 16;
    const float* Pp = P + (size_t)(m0 + lr) * Sdim + lc;
    int vr = t >> 3, vc = (t & 7) * 8;
    const float* Vp = V + (size_t)vr * DPT + vc;

    float acc[2][4][4];
    #pragma unroll
    for (int i = 0; i < 2; i++)
        #pragma unroll
        for (int j = 0; j < 4; j++)
            #pragma unroll
            for (int v = 0; v < 4; v++) acc[i][j][v] = 0.f;

    float4 pa[4];
    #pragma unroll
    for (int i = 0; i < 4; i++) pa[i] = *(const float4*)(Pp + 4*i);
    float4 pv0 = *(const float4*)(Vp);
    float4 pv1 = *(const float4*)(Vp + 4);

    for (int kt = 0; kt < Sdim; kt += 32) {
        __syncthreads();
        #pragma unroll
        for (int i = 0; i < 4; i++) {
            int kk = lc + 4*i;
            Ps[kk+0][lr] = f2tf(pa[i].x); Ps[kk+1][lr] = f2tf(pa[i].y);
            Ps[kk+2][lr] = f2tf(pa[i].z); Ps[kk+3][lr] = f2tf(pa[i].w);
        }
        Vs[vr][vc+0] = f2tf(pv0.x); Vs[vr][vc+1] = f2tf(pv0.y);
        Vs[vr][vc+2] = f2tf(pv0.z); Vs[vr][vc+3] = f2tf(pv0.w);
        Vs[vr][vc+4] = f2tf(pv1.x); Vs[vr][vc+5] = f2tf(pv1.y);
        Vs[vr][vc+6] = f2tf(pv1.z); Vs[vr][vc+7] = f2tf(pv1.w);
        __syncthreads();
        if (kt + 32 < Sdim) {
            #pragma unroll
            for (int i = 0; i < 4; i++) pa[i] = *(const float4*)(Pp + kt + 32 + 4*i);
            pv0 = *(const float4*)(Vp + (size_t)(kt + 32) * DPT);
            pv1 = *(const float4*)(Vp + (size_t)(kt + 32) * DPT + 4);
        }
        #pragma unroll
        for (int ks = 0; ks < 4; ks++) {
            uint32_t af[2][4], bf[4][2];
            #pragma unroll
            for (int mt = 0; mt < 2; mt++) {
                af[mt][0] = Ps[ks*8 + q][wm + mt*16 + r];
                af[mt][1] = Ps[ks*8 + q][wm + mt*16 + 8 + r];
                af[mt][2] = Ps[ks*8 + 4 + q][wm + mt*16 + r];
                af[mt][3] = Ps[ks*8 + 4 + q][wm + mt*16 + 8 + r];
            }
            #pragma unroll
            for (int nt = 0; nt < 4; nt++) {
                bf[nt][0] = Vs[ks*8 + q][wn + nt*8 + r];
                bf[nt][1] = Vs[ks*8 + 4 + q][wn + nt*8 + r];
            }
            #pragma unroll
            for (int mt = 0; mt < 2; mt++)
                #pragma unroll
                for (int nt = 0; nt < 4; nt++)
                    mma8(acc[mt][nt], af[mt], bf[nt]);
        }
    }

    int bb = bh >> 4, h = bh & 15;
    #pragma unroll
    for (int mt = 0; mt < 2; mt++) {
        #pragma unroll
        for (int nt = 0; nt < 4; nt++) {
            int s = m0 + wm + mt*16 + r;
            int dcol = wn + nt*8 + 2*q;
            float* a4 = acc[mt][nt];
            size_t base = ((size_t)bb * Sdim + s) * DMdim + h*DPT + dcol;
            *(float2*)&g_concat[base]            = make_float2(a4[0], a4[1]);
            *(float2*)&g_concat[base + 8*DMdim]  = make_float2(a4[2], a4[3]);
        }
    }
}

// ---------------------------------------------------------------------------
extern "C" void kernel_launch(void* const* d_in, const int* in_sizes, int n_in,
                              void* d_out, int out_size)
{
    const float* v_in    = (const float*)d_in[0];
    const float* k_in    = (const float*)d_in[1];
    const float* q_in    = (const float*)d_in[2];
    const float* mask    = (const float*)d_in[3];
    const float* wq_w    = (const float*)d_in[4];
    const float* wq_b    = (const float*)d_in[5];
    const float* wk_w    = (const float*)d_in[6];
    const float* wk_b    = (const float*)d_in[7];
    const float* wv_w    = (const float*)d_in[8];
    const float* wv_b    = (const float*)d_in[9];
    const float* dense_w = (const float*)d_in[10];
    const float* dense_b = (const float*)d_in[11];

    float *qh, *kh, *vh, *concat, *attn_chunk;
    cudaGetSymbolAddress((void**)&qh, g_qh);
    cudaGetSymbolAddress((void**)&kh, g_kh);
    cudaGetSymbolAddress((void**)&vh, g_vh);
    cudaGetSymbolAddress((void**)&concat, g_concat);
    cudaGetSymbolAddress((void**)&attn_chunk, g_attn_chunk);

    float* out = (float*)d_out;
    int attn_in_out = ((long long)out_size >= (long long)OUT_ELEMS + ATTN_ELEMS);

    dim3 blk(256);
    dim3 g_gemm(DMdim / 128, (Bdim * Sdim) / 128);   // (8, 64)

    gemm1024_tf32<1><<<g_gemm, blk>>>(q_in, wq_w, wq_b, qh);
    gemm1024_tf32<1><<<g_gemm, blk>>>(k_in, wk_w, wk_b, kh);
    gemm1024_tf32<1><<<g_gemm, blk>>>(v_in, wv_w, wv_b, vh);

    if (attn_in_out) {
        float* attn = out + OUT_ELEMS;
        qk_tf32<<<dim3(Sdim/128, Sdim/128, BHdim), blk>>>(mask, attn, 0);
        softmax_kernel<<<dim3(Sdim, BHdim), blk>>>(attn);
        pv_tf32<<<dim3(Sdim/128, BHdim), blk>>>(attn, 0);
    } else {
        for (int c = 0; c < BHdim; c += CHUNK_BH) {
            qk_tf32<<<dim3(Sdim/128, Sdim/128, CHUNK_BH), blk>>>(mask, attn_chunk, c);
            softmax_kernel<<<dim3(Sdim, CHUNK_BH), blk>>>(attn_chunk);
            pv_tf32<<<dim3(Sdim/128, CHUNK_BH), blk>>>(attn_chunk, c);
        }
    }

    gemm1024_tf32<0><<<g_gemm, blk>>>(concat, dense_w, dense_b, out);
}

// round 7
// speedup vs baseline: 2.2457x; 1.0675x over previous
#include <cuda_runtime.h>
#include <math.h>
#include <stdint.h>

// Problem dims
#define Bdim   4
#define Sdim   2048
#define DMdim  1024
#define Hdim   16
#define DPT    64
#define BHdim  (Bdim*Hdim)

#define OUT_ELEMS  (Bdim*Sdim*DMdim)                 // 8388608
#define ATTN_ELEMS ((long long)BHdim*Sdim*Sdim)      // 268435456
#define CHUNK_BH   4
#define NCTILE     16                                 // Sdim/128 col tiles

// Scratch (allocation-free: __device__ globals). ~206 MB total.
__device__ float g_qh[(size_t)BHdim*Sdim*DPT];
__device__ float g_kh[(size_t)BHdim*Sdim*DPT];
__device__ float g_vh[(size_t)BHdim*Sdim*DPT];
__device__ float g_concat[(size_t)Bdim*Sdim*DMdim];
__device__ float g_psum[(size_t)BHdim*Sdim*NCTILE];  // per-(row, col-tile) exp sums, 8 MB
__device__ float g_attn_chunk[(size_t)CHUNK_BH*Sdim*Sdim];

// ---------------------------------------------------------------------------
__device__ __forceinline__ uint32_t f2tf(float x) {
    uint32_t r;
    asm("cvt.rna.tf32.f32 %0, %1;" : "=r"(r) : "f"(x));
    return r;
}

__device__ __forceinline__ void mma8(float* c, const uint32_t* a, const uint32_t* b) {
    asm volatile(
        "mma.sync.aligned.m16n8k8.row.col.f32.tf32.tf32.f32 "
        "{%0,%1,%2,%3},{%4,%5,%6,%7},{%8,%9},{%0,%1,%2,%3};\n"
        : "+f"(c[0]), "+f"(c[1]), "+f"(c[2]), "+f"(c[3])
        : "r"(a[0]), "r"(a[1]), "r"(a[2]), "r"(a[3]), "r"(b[0]), "r"(b[1]));
}

// ---------------------------------------------------------------------------
// tf32 GEMM: C(128x128/block) = A(MxK) @ W(NxK)^T (+bias), K=1024
// EPI: 0 = dense row-major (M x DMdim), 1 = head-scatter to (B,H,S,DPT)
// ---------------------------------------------------------------------------
template<int EPI>
__global__ void __launch_bounds__(256, 2)
gemm1024_tf32(const float* __restrict__ A, const float* __restrict__ W,
              const float* __restrict__ bias, float* __restrict__ out)
{
    const int K = 1024;
    __shared__ uint32_t As[16][136];   // [k][m]
    __shared__ uint32_t Bs[16][136];   // [k][n]
    int t = threadIdx.x, lane = t & 31, w = t >> 5;
    int q = lane & 3, r = lane >> 2;
    int m0 = blockIdx.y * 128, n0 = blockIdx.x * 128;
    int wm = (w & 1) * 64, wn = (w >> 1) * 32;
    int lr = t >> 1, lc = (t & 1) * 4;
    const float* Ap = A + (size_t)(m0 + lr) * K + lc;
    const float* Wp = W + (size_t)(n0 + lr) * K + lc;

    float acc[4][4][4];
    #pragma unroll
    for (int i = 0; i < 4; i++)
        #pragma unroll
        for (int j = 0; j < 4; j++)
            #pragma unroll
            for (int v = 0; v < 4; v++) acc[i][j][v] = 0.f;

    float4 pa0 = *(const float4*)Ap,      pa1 = *(const float4*)(Ap + 8);
    float4 pb0 = *(const float4*)Wp,      pb1 = *(const float4*)(Wp + 8);

    for (int kt = 0; kt < K; kt += 16) {
        __syncthreads();
        As[lc+0][lr]=f2tf(pa0.x); As[lc+1][lr]=f2tf(pa0.y); As[lc+2][lr]=f2tf(pa0.z); As[lc+3][lr]=f2tf(pa0.w);
        As[lc+8][lr]=f2tf(pa1.x); As[lc+9][lr]=f2tf(pa1.y); As[lc+10][lr]=f2tf(pa1.z); As[lc+11][lr]=f2tf(pa1.w);
        Bs[lc+0][lr]=f2tf(pb0.x); Bs[lc+1][lr]=f2tf(pb0.y); Bs[lc+2][lr]=f2tf(pb0.z); Bs[lc+3][lr]=f2tf(pb0.w);
        Bs[lc+8][lr]=f2tf(pb1.x); Bs[lc+9][lr]=f2tf(pb1.y); Bs[lc+10][lr]=f2tf(pb1.z); Bs[lc+11][lr]=f2tf(pb1.w);
        __syncthreads();
        if (kt + 16 < K) {
            pa0 = *(const float4*)(Ap + kt + 16); pa1 = *(const float4*)(Ap + kt + 24);
            pb0 = *(const float4*)(Wp + kt + 16); pb1 = *(const float4*)(Wp + kt + 24);
        }
        #pragma unroll
        for (int ks = 0; ks < 2; ks++) {
            uint32_t af[4][4], bf[4][2];
            #pragma unroll
            for (int mt = 0; mt < 4; mt++) {
                af[mt][0] = As[ks*8 + q][wm + mt*16 + r];
                af[mt][1] = As[ks*8 + q][wm + mt*16 + 8 + r];
                af[mt][2] = As[ks*8 + 4 + q][wm + mt*16 + r];
                af[mt][3] = As[ks*8 + 4 + q][wm + mt*16 + 8 + r];
            }
            #pragma unroll
            for (int nt = 0; nt < 4; nt++) {
                bf[nt][0] = Bs[ks*8 + q][wn + nt*8 + r];
                bf[nt][1] = Bs[ks*8 + 4 + q][wn + nt*8 + r];
            }
            #pragma unroll
            for (int mt = 0; mt < 4; mt++)
                #pragma unroll
                for (int nt = 0; nt < 4; nt++)
                    mma8(acc[mt][nt], af[mt], bf[nt]);
        }
    }

    #pragma unroll
    for (int mt = 0; mt < 4; mt++) {
        #pragma unroll
        for (int nt = 0; nt < 4; nt++) {
            int m = m0 + wm + mt*16 + r;
            int n = n0 + wn + nt*8 + 2*q;
            float* a4 = acc[mt][nt];
            float bv0 = bias[n], bv1 = bias[n+1];
            if (EPI == 0) {
                *(float2*)&out[(size_t)m*DMdim + n]     = make_float2(a4[0]+bv0, a4[1]+bv1);
                *(float2*)&out[(size_t)(m+8)*DMdim + n] = make_float2(a4[2]+bv0, a4[3]+bv1);
            } else {
                int bb = m >> 11, s = m & 2047, h = n >> 6, d = n & 63;
                size_t base = ((size_t)(bb*Hdim + h)) * Sdim;
                *(float2*)&out[(base + s)*DPT + d]     = make_float2(a4[0]+bv0, a4[1]+bv1);
                *(float2*)&out[(base + s + 8)*DPT + d] = make_float2(a4[2]+bv0, a4[3]+bv1);
            }
        }
    }
}

// ---------------------------------------------------------------------------
// QK^T (tf32) + fused exp:  P = exp(Q@K^T * 0.125 + mask*(-1e9))
// (no max-subtraction: logits are O(1); masked -> exp underflows to 0).
// Writes unnormalized P to attn and per-(row, col-tile) sums to g_psum.
// ---------------------------------------------------------------------------
__global__ void __launch_bounds__(256, 2)
qk_tf32(const float* __restrict__ mask, float* __restrict__ attn, int bh_base)
{
    const int K = DPT;
    __shared__ uint32_t As[16][136];
    __shared__ uint32_t Bs[16][136];
    __shared__ float sred[128][4];
    int t = threadIdx.x, lane = t & 31, w = t >> 5;
    int q = lane & 3, r = lane >> 2;
    int zl = blockIdx.z, bh = bh_base + zl;
    int m0 = blockIdx.y * 128, n0 = blockIdx.x * 128;
    int wm = (w & 1) * 64, wn = (w >> 1) * 32;
    int wnidx = w >> 1;
    int lr = t >> 1, lc = (t & 1) * 4;
    const float* Q  = g_qh + (size_t)bh * Sdim * DPT;
    const float* Kh = g_kh + (size_t)bh * Sdim * DPT;
    const float* Ap = Q  + (size_t)(m0 + lr) * K + lc;
    const float* Wp = Kh + (size_t)(n0 + lr) * K + lc;

    float acc[4][4][4];
    #pragma unroll
    for (int i = 0; i < 4; i++)
        #pragma unroll
        for (int j = 0; j < 4; j++)
            #pragma unroll
            for (int v = 0; v < 4; v++) acc[i][j][v] = 0.f;

    float4 pa0 = *(const float4*)Ap, pa1 = *(const float4*)(Ap + 8);
    float4 pb0 = *(const float4*)Wp, pb1 = *(const float4*)(Wp + 8);

    #pragma unroll
    for (int kt = 0; kt < K; kt += 16) {
        __syncthreads();
        As[lc+0][lr]=f2tf(pa0.x); As[lc+1][lr]=f2tf(pa0.y); As[lc+2][lr]=f2tf(pa0.z); As[lc+3][lr]=f2tf(pa0.w);
        As[lc+8][lr]=f2tf(pa1.x); As[lc+9][lr]=f2tf(pa1.y); As[lc+10][lr]=f2tf(pa1.z); As[lc+11][lr]=f2tf(pa1.w);
        Bs[lc+0][lr]=f2tf(pb0.x); Bs[lc+1][lr]=f2tf(pb0.y); Bs[lc+2][lr]=f2tf(pb0.z); Bs[lc+3][lr]=f2tf(pb0.w);
        Bs[lc+8][lr]=f2tf(pb1.x); Bs[lc+9][lr]=f2tf(pb1.y); Bs[lc+10][lr]=f2tf(pb1.z); Bs[lc+11][lr]=f2tf(pb1.w);
        __syncthreads();
        if (kt + 16 < K) {
            pa0 = *(const float4*)(Ap + kt + 16); pa1 = *(const float4*)(Ap + kt + 24);
            pb0 = *(const float4*)(Wp + kt + 16); pb1 = *(const float4*)(Wp + kt + 24);
        }
        #pragma unroll
        for (int ks = 0; ks < 2; ks++) {
            uint32_t af[4][4], bf[4][2];
            #pragma unroll
            for (int mt = 0; mt < 4; mt++) {
                af[mt][0] = As[ks*8 + q][wm + mt*16 + r];
                af[mt][1] = As[ks*8 + q][wm + mt*16 + 8 + r];
                af[mt][2] = As[ks*8 + 4 + q][wm + mt*16 + r];
                af[mt][3] = As[ks*8 + 4 + q][wm + mt*16 + 8 + r];
            }
            #pragma unroll
            for (int nt = 0; nt < 4; nt++) {
                bf[nt][0] = Bs[ks*8 + q][wn + nt*8 + r];
                bf[nt][1] = Bs[ks*8 + 4 + q][wn + nt*8 + r];
            }
            #pragma unroll
            for (int mt = 0; mt < 4; mt++)
                #pragma unroll
                for (int nt = 0; nt < 4; nt++)
                    mma8(acc[mt][nt], af[mt], bf[nt]);
        }
    }

    const float* mrow = mask + (size_t)(bh >> 4) * Sdim;
    float* orow = attn + (size_t)zl * Sdim * Sdim;
    float rsum[8];
    #pragma unroll
    for (int i = 0; i < 8; i++) rsum[i] = 0.f;

    #pragma unroll
    for (int mt = 0; mt < 4; mt++) {
        #pragma unroll
        for (int nt = 0; nt < 4; nt++) {
            int m = m0 + wm + mt*16 + r;
            int n = n0 + wn + nt*8 + 2*q;
            float* a4 = acc[mt][nt];
            float mk0 = mrow[n] * (-1e9f), mk1 = mrow[n+1] * (-1e9f);
            float p0 = expf(a4[0]*0.125f + mk0);
            float p1 = expf(a4[1]*0.125f + mk1);
            float p2 = expf(a4[2]*0.125f + mk0);
            float p3 = expf(a4[3]*0.125f + mk1);
            *(float2*)&orow[(size_t)m*Sdim + n]     = make_float2(p0, p1);
            *(float2*)&orow[(size_t)(m+8)*Sdim + n] = make_float2(p2, p3);
            rsum[mt*2+0] += p0 + p1;
            rsum[mt*2+1] += p2 + p3;
        }
    }
    // reduce over q lanes (lanes 4r+q share rows)
    #pragma unroll
    for (int i = 0; i < 8; i++) {
        rsum[i] += __shfl_xor_sync(0xffffffffu, rsum[i], 1);
        rsum[i] += __shfl_xor_sync(0xffffffffu, rsum[i], 2);
    }
    if (q == 0) {
        #pragma unroll
        for (int mt = 0; mt < 4; mt++) {
            sred[wm + mt*16 + r][wnidx]     = rsum[mt*2+0];
            sred[wm + mt*16 + 8 + r][wnidx] = rsum[mt*2+1];
        }
    }
    __syncthreads();
    if (t < 128) {
        float s = sred[t][0] + sred[t][1] + sred[t][2] + sred[t][3];
        g_psum[((size_t)bh * Sdim + m0 + t) * NCTILE + blockIdx.x] = s;
    }
}

// ---------------------------------------------------------------------------
// PV (tf32) + fused normalize: inv = 1/rowsum; normalized P written back to
// attn in place (each element owned by exactly one CTA); ctx = Pn @ V into
// g_concat (B,S,DM) head-interleaved.
// ---------------------------------------------------------------------------
__global__ void __launch_bounds__(256, 2)
pv_tf32(float* __restrict__ attn, int bh_base)
{
    __shared__ uint32_t Ps[32][136];   // [k][m]
    __shared__ uint32_t Vs[32][72];    // [k][n]
    __shared__ float sinv[128];
    int t = threadIdx.x, lane = t & 31, w = t >> 5;
    int q = lane & 3, r = lane >> 2;
    int zl = blockIdx.y, bh = bh_base + zl;
    int m0 = blockIdx.x * 128;
    int wm = (w & 3) * 32, wn = (w >> 2) * 32;
    float* P = attn + (size_t)zl * Sdim * Sdim;
    const float* V = g_vh + (size_t)bh * Sdim * DPT;

    // row inverse sums from qk partials
    if (t < 128) {
        const float* pp = &g_psum[((size_t)bh * Sdim + m0 + t) * NCTILE];
        float s = 0.f;
        #pragma unroll
        for (int i = 0; i < NCTILE; i++) s += pp[i];
        sinv[t] = 1.0f / s;
    }
    __syncthreads();

    int lr = t >> 1, lc = (t & 1) * 16;
    float* Pp = P + (size_t)(m0 + lr) * Sdim + lc;
    int vr = t >> 3, vc = (t & 7) * 8;
    const float* Vp = V + (size_t)vr * DPT + vc;
    float inv_r = sinv[lr];

    float acc[2][4][4];
    #pragma unroll
    for (int i = 0; i < 2; i++)
        #pragma unroll
        for (int j = 0; j < 4; j++)
            #pragma unroll
            for (int v = 0; v < 4; v++) acc[i][j][v] = 0.f;

    float4 pa[4];
    #pragma unroll
    for (int i = 0; i < 4; i++) pa[i] = *(const float4*)(Pp + 4*i);
    float4 pv0 = *(const float4*)(Vp);
    float4 pv1 = *(const float4*)(Vp + 4);

    for (int kt = 0; kt < Sdim; kt += 32) {
        // normalize this thread's P slice
        float4 sa[4];
        #pragma unroll
        for (int i = 0; i < 4; i++) {
            sa[i].x = pa[i].x * inv_r; sa[i].y = pa[i].y * inv_r;
            sa[i].z = pa[i].z * inv_r; sa[i].w = pa[i].w * inv_r;
        }
        // write normalized P back to attn (final output values)
        #pragma unroll
        for (int i = 0; i < 4; i++)
            *(float4*)(Pp + kt + 4*i) = sa[i];

        __syncthreads();
        #pragma unroll
        for (int i = 0; i < 4; i++) {
            int kk = lc + 4*i;
            Ps[kk+0][lr] = f2tf(sa[i].x); Ps[kk+1][lr] = f2tf(sa[i].y);
            Ps[kk+2][lr] = f2tf(sa[i].z); Ps[kk+3][lr] = f2tf(sa[i].w);
        }
        Vs[vr][vc+0] = f2tf(pv0.x); Vs[vr][vc+1] = f2tf(pv0.y);
        Vs[vr][vc+2] = f2tf(pv0.z); Vs[vr][vc+3] = f2tf(pv0.w);
        Vs[vr][vc+4] = f2tf(pv1.x); Vs[vr][vc+5] = f2tf(pv1.y);
        Vs[vr][vc+6] = f2tf(pv1.z); Vs[vr][vc+7] = f2tf(pv1.w);
        __syncthreads();
        if (kt + 32 < Sdim) {
            #pragma unroll
            for (int i = 0; i < 4; i++) pa[i] = *(const float4*)(Pp + kt + 32 + 4*i);
            pv0 = *(const float4*)(Vp + (size_t)(kt + 32) * DPT);
            pv1 = *(const float4*)(Vp + (size_t)(kt + 32) * DPT + 4);
        }
        #pragma unroll
        for (int ks = 0; ks < 4; ks++) {
            uint32_t af[2][4], bf[4][2];
            #pragma unroll
            for (int mt = 0; mt < 2; mt++) {
                af[mt][0] = Ps[ks*8 + q][wm + mt*16 + r];
                af[mt][1] = Ps[ks*8 + q][wm + mt*16 + 8 + r];
                af[mt][2] = Ps[ks*8 + 4 + q][wm + mt*16 + r];
                af[mt][3] = Ps[ks*8 + 4 + q][wm + mt*16 + 8 + r];
            }
            #pragma unroll
            for (int nt = 0; nt < 4; nt++) {
                bf[nt][0] = Vs[ks*8 + q][wn + nt*8 + r];
                bf[nt][1] = Vs[ks*8 + 4 + q][wn + nt*8 + r];
            }
            #pragma unroll
            for (int mt = 0; mt < 2; mt++)
                #pragma unroll
                for (int nt = 0; nt < 4; nt++)
                    mma8(acc[mt][nt], af[mt], bf[nt]);
        }
    }

    int bb = bh >> 4, h = bh & 15;
    #pragma unroll
    for (int mt = 0; mt < 2; mt++) {
        #pragma unroll
        for (int nt = 0; nt < 4; nt++) {
            int s = m0 + wm + mt*16 + r;
            int dcol = wn + nt*8 + 2*q;
            float* a4 = acc[mt][nt];
            size_t base = ((size_t)bb * Sdim + s) * DMdim + h*DPT + dcol;
            *(float2*)&g_concat[base]            = make_float2(a4[0], a4[1]);
            *(float2*)&g_concat[base + 8*DMdim]  = make_float2(a4[2], a4[3]);
        }
    }
}

// ---------------------------------------------------------------------------
extern "C" void kernel_launch(void* const* d_in, const int* in_sizes, int n_in,
                              void* d_out, int out_size)
{
    const float* v_in    = (const float*)d_in[0];
    const float* k_in    = (const float*)d_in[1];
    const float* q_in    = (const float*)d_in[2];
    const float* mask    = (const float*)d_in[3];
    const float* wq_w    = (const float*)d_in[4];
    const float* wq_b    = (const float*)d_in[5];
    const float* wk_w    = (const float*)d_in[6];
    const float* wk_b    = (const float*)d_in[7];
    const float* wv_w    = (const float*)d_in[8];
    const float* wv_b    = (const float*)d_in[9];
    const float* dense_w = (const float*)d_in[10];
    const float* dense_b = (const float*)d_in[11];

    float *qh, *kh, *vh, *concat, *attn_chunk;
    cudaGetSymbolAddress((void**)&qh, g_qh);
    cudaGetSymbolAddress((void**)&kh, g_kh);
    cudaGetSymbolAddress((void**)&vh, g_vh);
    cudaGetSymbolAddress((void**)&concat, g_concat);
    cudaGetSymbolAddress((void**)&attn_chunk, g_attn_chunk);

    float* out = (float*)d_out;
    int attn_in_out = ((long long)out_size >= (long long)OUT_ELEMS + ATTN_ELEMS);

    dim3 blk(256);
    dim3 g_gemm(DMdim / 128, (Bdim * Sdim) / 128);   // (8, 64)

    gemm1024_tf32<1><<<g_gemm, blk>>>(q_in, wq_w, wq_b, qh);
    gemm1024_tf32<1><<<g_gemm, blk>>>(k_in, wk_w, wk_b, kh);
    gemm1024_tf32<1><<<g_gemm, blk>>>(v_in, wv_w, wv_b, vh);

    if (attn_in_out) {
        float* attn = out + OUT_ELEMS;
        qk_tf32<<<dim3(NCTILE, Sdim/128, BHdim), blk>>>(mask, attn, 0);
        pv_tf32<<<dim3(Sdim/128, BHdim), blk>>>(attn, 0);
    } else {
        for (int c = 0; c < BHdim; c += CHUNK_BH) {
            qk_tf32<<<dim3(NCTILE, Sdim/128, CHUNK_BH), blk>>>(mask, attn_chunk, c);
            pv_tf32<<<dim3(Sdim/128, CHUNK_BH), blk>>>(attn_chunk, c);
        }
    }

    gemm1024_tf32<0><<<g_gemm, blk>>>(concat, dense_w, dense_b, out);
}